// round 14
// baseline (speedup 1.0000x reference)
#include <cuda_runtime.h>
#include <cuda_fp16.h>
#include <cstdint>
#include <math.h>

#define N_OBJ   2048
#define N_REL   32768
#define FEAT    2048
#define DIM     512
#define NC_OBJ  151
#define NC_PRED 51
#define PS_P    128      // padded pitch for pred scores
#define SC_HALF 256      // score scatter half width

typedef unsigned short u16;

// ---------------- fp32 scratch ------------------------------------------------
__device__ __align__(128) float g_pfeatA[N_REL*DIM];
__device__ __align__(128) float g_pfeatB[N_REL*DIM];
__device__ __align__(128) float g_ofeatA[N_OBJ*DIM];
__device__ __align__(128) float g_ofeatB[N_OBJ*DIM];
__device__ __align__(128) float g_fcoCat[N_OBJ*2*DIM];
__device__ __align__(128) float g_accCat[2*N_OBJ*DIM];
__device__ __align__(128) float g_osA   [N_OBJ*NC_OBJ];
__device__ __align__(128) float g_osB   [N_OBJ*NC_OBJ];
__device__ __align__(128) float g_psA   [N_REL*PS_P];
__device__ __align__(128) float g_psB   [N_REL*PS_P];
__device__ __align__(128) float g_fcs0  [N_OBJ*NC_PRED];
__device__ __align__(128) float g_fcs1  [N_OBJ*NC_PRED];
__device__ __align__(128) float g_deg   [2*N_OBJ];
__device__ __align__(128) float g_bsoC  [2*SC_HALF];
__device__ __align__(128) float g_bpcP  [PS_P];

// ---------------- fp16 operand buffers ----------------------------------------
__device__ __align__(128) u16 g_xo  [N_OBJ*FEAT];
__device__ __align__(128) u16 g_xp  [N_REL*FEAT];
__device__ __align__(128) u16 g_hob [N_OBJ*DIM];
__device__ __align__(128) u16 g_hpr [N_REL*DIM];
__device__ __align__(128) u16 g_pfh [N_REL*DIM];
__device__ __align__(128) u16 g_psh [N_REL*PS_P];
__device__ __align__(128) u16 g_ofh0[N_OBJ*DIM];
__device__ __align__(128) u16 g_ofh1[N_OBJ*DIM];
__device__ __align__(128) u16 g_oW1f[FEAT*DIM];
__device__ __align__(128) u16 g_oW2f[DIM*DIM];
__device__ __align__(128) u16 g_rW1f[FEAT*DIM];
__device__ __align__(128) u16 g_rW2f[DIM*DIM];
__device__ __align__(128) u16 g_Wcat01[DIM*2*DIM];
__device__ __align__(128) u16 g_Wcat23[DIM*2*DIM];
__device__ __align__(128) u16 g_WsoC[PS_P*2*SC_HALF];
__device__ __align__(128) u16 g_WpcP[DIM*PS_P];

// ---------------- helpers ------------------------------------------------------
__device__ __forceinline__ uint32_t smem_u32(const void* p) {
    uint32_t a;
    asm("{ .reg .u64 t; cvta.to.shared.u64 t, %1; cvt.u32.u64 %0, t; }" : "=r"(a) : "l"(p));
    return a;
}
__device__ __forceinline__ uint32_t pack_h2(float x, float y) {
    uint32_t d;
    asm("cvt.rn.f16x2.f32 %0, %1, %2;" : "=r"(d) : "f"(y), "f"(x));
    return d;
}
__device__ __forceinline__ void ldsm_x4(uint32_t* r, uint32_t addr) {
    asm volatile("ldmatrix.sync.aligned.m8n8.x4.shared.b16 {%0,%1,%2,%3}, [%4];"
                 : "=r"(r[0]), "=r"(r[1]), "=r"(r[2]), "=r"(r[3]) : "r"(addr));
}
__device__ __forceinline__ void ldsm_x4_t(uint32_t* r, uint32_t addr) {
    asm volatile("ldmatrix.sync.aligned.m8n8.x4.trans.shared.b16 {%0,%1,%2,%3}, [%4];"
                 : "=r"(r[0]), "=r"(r[1]), "=r"(r[2]), "=r"(r[3]) : "r"(addr));
}
__device__ __forceinline__ void mma16816(float* c, const uint32_t* a, uint32_t b0, uint32_t b1) {
    asm volatile("mma.sync.aligned.m16n8k16.row.col.f32.f16.f16.f32 "
                 "{%0,%1,%2,%3}, {%4,%5,%6,%7}, {%8,%9}, {%0,%1,%2,%3};"
                 : "+f"(c[0]), "+f"(c[1]), "+f"(c[2]), "+f"(c[3])
                 : "r"(a[0]), "r"(a[1]), "r"(a[2]), "r"(a[3]), "r"(b0), "r"(b1));
}
__device__ __forceinline__ void cp16(uint32_t dst, const void* src) {
    asm volatile("cp.async.cg.shared.global [%0], [%1], 16;" :: "r"(dst), "l"(src) : "memory");
}
#define CP_COMMIT() asm volatile("cp.async.commit_group;" ::: "memory")
#define CP_WAIT1()  asm volatile("cp.async.wait_group 1;" ::: "memory")
#define CP_WAIT2()  asm volatile("cp.async.wait_group 2;" ::: "memory")

// epilogue helper shared by tensor kernels
__device__ __forceinline__ void epi_quad(
    float* a, int r0, int r1, int c, int N, int doRelu,
    const float* bias, float* C, u16* Ch,
    float* saccB, int t0, int t1, int shalf, int side) {
    float b0 = bias[c], b1 = bias[c + 1];
    float v0 = a[0] + b0, v1 = a[1] + b1, v2 = a[2] + b0, v3 = a[3] + b1;
    if (doRelu) {
        v0 = fmaxf(v0, 0.0f); v1 = fmaxf(v1, 0.0f);
        v2 = fmaxf(v2, 0.0f); v3 = fmaxf(v3, 0.0f);
    }
    if (saccB) {
        const int col = c - side * shalf;
        atomicAdd(&saccB[(size_t)t0 * shalf + col],     v0);
        atomicAdd(&saccB[(size_t)t0 * shalf + col + 1], v1);
        atomicAdd(&saccB[(size_t)t1 * shalf + col],     v2);
        atomicAdd(&saccB[(size_t)t1 * shalf + col + 1], v3);
    } else {
        if (C) {
            *(float2*)(C + (size_t)r0 * N + c) = make_float2(v0, v1);
            *(float2*)(C + (size_t)r1 * N + c) = make_float2(v2, v3);
        }
        if (Ch) {
            *(uint32_t*)(Ch + (size_t)r0 * N + c) = pack_h2(v0, v1);
            *(uint32_t*)(Ch + (size_t)r1 * N + c) = pack_h2(v2, v3);
        }
    }
}

// ================== QUAD GEMM: CTA 128x128, 4 warps 64x64, K-tile 64, 3-stage ===
// Requires K%64==0. If sacc: fused dual scatter [2][N_OBJ][shalf], side=n0/shalf.
#define QAPITCH 144     // 64 f16 = 128B + 16B pad (9 x 16B -> conflict-free ldsm)
#define BPITCH  272     // 128 f16 = 256B + 16B pad
#define QST_A   0
#define QST_B   18432
#define QST_SZ  35840
#define SMEM_GEMMQ (3*QST_SZ)

__global__ __launch_bounds__(128, 2)
void gemm_f16q(const u16* __restrict__ A, const u16* __restrict__ B,
               const float* __restrict__ bias, int M, int K, int N, int doRelu,
               float* __restrict__ C, u16* __restrict__ Ch,
               const int* __restrict__ rel, float* __restrict__ sacc, int shalf) {
    extern __shared__ __align__(128) char smem[];
    const uint32_t sb = smem_u32(smem);
    const int tid = threadIdx.x;
    const int lane = tid & 31;
    const int w = tid >> 5;
    const int warp_m = (w & 1) * 64;
    const int warp_n = (w >> 1) * 64;
    const int m0 = blockIdx.y * 128;
    const int n0 = blockIdx.x * 128;
    const int KT = K >> 6;

    float acc[32][4];
    #pragma unroll
    for (int i = 0; i < 32; i++)
        #pragma unroll
        for (int j = 0; j < 4; j++) acc[i][j] = 0.0f;

    // stage slot for kt: kt % 3
    auto issue = [&](int kt, int slot) {
        const uint32_t st = sb + slot * QST_SZ;
        // A: 128 rows x 8 chunks = 1024 cp16 -> 8/thread
        #pragma unroll
        for (int i = 0; i < 8; i++) {
            int idx = i * 128 + tid;
            int arow = idx >> 3, ac = idx & 7;
            size_t ga = (size_t)(m0 + arow) * K + kt * 64 + ac * 8;
            cp16(st + QST_A + (uint32_t)(arow * QAPITCH + ac * 16), A + ga);
        }
        // B: 64 rows x 16 chunks = 1024 cp16 -> 8/thread
        #pragma unroll
        for (int i = 0; i < 8; i++) {
            int idx = i * 128 + tid;
            int brow = idx >> 4, bc = idx & 15;
            size_t gb = (size_t)(kt * 64 + brow) * N + n0 + bc * 8;
            cp16(st + QST_B + (uint32_t)(brow * BPITCH + bc * 16), B + gb);
        }
    };

    issue(0, 0); CP_COMMIT();
    if (KT > 1) issue(1, 1);
    CP_COMMIT();

    int slot = 0, nslot = 2;   // slot of kt; next slot to fill
    for (int kt = 0; kt < KT; kt++) {
        CP_WAIT1();
        __syncthreads();
        if (kt + 2 < KT) issue(kt + 2, nslot);
        CP_COMMIT();

        const uint32_t st = sb + slot * QST_SZ;
        #pragma unroll
        for (int ks = 0; ks < 4; ks++) {
            uint32_t ah[4][4];
            const uint32_t a_off = (uint32_t)((warp_m + (lane & 15)) * QAPITCH
                                              + ks * 32 + (lane >> 4) * 16);
            #pragma unroll
            for (int mi = 0; mi < 4; mi++)
                ldsm_x4(ah[mi], st + QST_A + a_off + mi * 16 * QAPITCH);
            const uint32_t b_off = (uint32_t)((ks * 16 + (lane & 15)) * BPITCH
                                              + (warp_n + (lane >> 4) * 8) * 2);
            #pragma unroll
            for (int np = 0; np < 4; np++) {
                uint32_t bh[4];
                ldsm_x4_t(bh, st + QST_B + b_off + np * 32);
                #pragma unroll
                for (int mi = 0; mi < 4; mi++) {
                    #pragma unroll
                    for (int j = 0; j < 2; j++)
                        mma16816(acc[mi * 8 + np * 2 + j], ah[mi], bh[2*j], bh[2*j+1]);
                }
            }
        }
        slot = (slot == 2) ? 0 : slot + 1;
        nslot = (nslot == 2) ? 0 : nslot + 1;
    }

    const int g = lane >> 2, tig = lane & 3;
    float* saccB = nullptr;
    int side = 0;
    if (sacc) { side = n0 / shalf; saccB = sacc + (size_t)side * N_OBJ * shalf; }
    #pragma unroll
    for (int mi = 0; mi < 4; mi++) {
        const int r0 = m0 + warp_m + mi * 16 + g;
        const int r1 = r0 + 8;
        int t0 = 0, t1 = 0;
        if (sacc) { t0 = rel[r0 * 2 + side]; t1 = rel[r1 * 2 + side]; }
        #pragma unroll
        for (int ni = 0; ni < 8; ni++) {
            const int c = n0 + warp_n + ni * 8 + tig * 2;
            epi_quad(acc[mi * 8 + ni], r0, r1, c, N, doRelu, bias, C, Ch,
                     saccB, t0, t1, shalf, side);
        }
    }
}

// ================== HALF-M GEMM: CTA 64x128, 4 warps 32x64, 4 CTA/SM ===========
#define APITCH 80
#define HST_A 0
#define HST_B 5120
#define HST_SZ 13824

__global__ __launch_bounds__(128, 4)
void gemm_f16h(const u16* __restrict__ A, const u16* __restrict__ B,
               const float* __restrict__ bias, int M, int K, int N, int doRelu,
               float* __restrict__ C, u16* __restrict__ Ch) {
    extern __shared__ __align__(128) char smem[];
    const uint32_t sb = smem_u32(smem);
    const int tid = threadIdx.x;
    const int lane = tid & 31;
    const int w = tid >> 5;
    const int warp_m = (w & 1) * 32;
    const int warp_n = (w >> 1) * 64;
    const int m0 = blockIdx.y * 64;
    const int n0 = blockIdx.x * 128;
    const int KT = K >> 5;

    float acc[16][4];
    #pragma unroll
    for (int i = 0; i < 16; i++)
        #pragma unroll
        for (int j = 0; j < 4; j++) acc[i][j] = 0.0f;

    auto issue = [&](int kt) {
        const uint32_t st = sb + (kt & 3) * HST_SZ;
        #pragma unroll
        for (int i = 0; i < 2; i++) {
            int idx = i * 128 + tid;
            int arow = idx >> 2, ac = idx & 3;
            size_t ga = (size_t)(m0 + arow) * K + kt * 32 + ac * 8;
            cp16(st + HST_A + (uint32_t)(arow * APITCH + ac * 16), A + ga);
        }
        #pragma unroll
        for (int i = 0; i < 4; i++) {
            int idx = i * 128 + tid;
            int brow = idx >> 4, bc = idx & 15;
            size_t gb = (size_t)(kt * 32 + brow) * N + n0 + bc * 8;
            cp16(st + HST_B + (uint32_t)(brow * BPITCH + bc * 16), B + gb);
        }
    };

    issue(0); CP_COMMIT();
    issue(1); CP_COMMIT();
    issue(2); CP_COMMIT();

    for (int kt = 0; kt < KT; kt++) {
        CP_WAIT2();
        __syncthreads();
        if (kt + 3 < KT) issue(kt + 3);
        CP_COMMIT();

        const uint32_t st = sb + (kt & 3) * HST_SZ;
        #pragma unroll
        for (int ks = 0; ks < 2; ks++) {
            uint32_t ah[2][4];
            const uint32_t a_off = (uint32_t)((warp_m + (lane & 15)) * APITCH
                                              + ks * 32 + (lane >> 4) * 16);
            #pragma unroll
            for (int mi = 0; mi < 2; mi++)
                ldsm_x4(ah[mi], st + HST_A + a_off + mi * 16 * APITCH);
            const uint32_t b_off = (uint32_t)((ks * 16 + (lane & 15)) * BPITCH
                                              + (warp_n + (lane >> 4) * 8) * 2);
            #pragma unroll
            for (int np = 0; np < 4; np++) {
                uint32_t bh[4];
                ldsm_x4_t(bh, st + HST_B + b_off + np * 32);
                #pragma unroll
                for (int mi = 0; mi < 2; mi++) {
                    #pragma unroll
                    for (int j = 0; j < 2; j++)
                        mma16816(acc[mi * 8 + np * 2 + j], ah[mi], bh[2*j], bh[2*j+1]);
                }
            }
        }
    }

    const int g = lane >> 2, tig = lane & 3;
    #pragma unroll
    for (int mi = 0; mi < 2; mi++) {
        const int r0 = m0 + warp_m + mi * 16 + g;
        const int r1 = r0 + 8;
        #pragma unroll
        for (int ni = 0; ni < 8; ni++) {
            const int c = n0 + warp_n + ni * 8 + tig * 2;
            epi_quad(acc[mi * 8 + ni], r0, r1, c, N, doRelu, bias, C, Ch,
                     nullptr, 0, 0, 0, 0);
        }
    }
}

// ---------------- converters / packers ------------------------------------------
__global__ void conv_kernel(const float* __restrict__ x, u16* __restrict__ h, int n4) {
    int i = blockIdx.x * blockDim.x + threadIdx.x;
    if (i >= n4) return;
    float4 v = *(const float4*)(x + i * 4);
    uint2 o;
    o.x = pack_h2(v.x, v.y);
    o.y = pack_h2(v.z, v.w);
    *(uint2*)(h + i * 4) = o;
}
__global__ void packW_kernel(const float* __restrict__ W, u16* __restrict__ out, int base) {
    int i = blockIdx.x * blockDim.x + threadIdx.x;
    if (i >= DIM * DIM) return;
    int idx = i * 2;
    int k = idx >> 10, c = idx & 1023;
    int s = c >> 9, n = c & 511;
    const float* src = W + ((size_t)(base + s)) * DIM * DIM + (size_t)k * DIM + n;
    *(uint32_t*)(out + idx) = pack_h2(src[0], src[1]);
}
__global__ void packScore_kernel(const float* __restrict__ Wpc, const float* __restrict__ bpc,
                                 const float* __restrict__ Wso, const float* __restrict__ bso,
                                 u16* __restrict__ WpcP, float* __restrict__ bpcP,
                                 u16* __restrict__ WsoC, float* __restrict__ bsoC) {
    int i = blockIdx.x * blockDim.x + threadIdx.x;
    if (i < DIM * PS_P) {
        int k = i >> 7, n = i & 127;
        float v = (n < NC_PRED) ? Wpc[k * NC_PRED + n] : 0.0f;
        __half h = __float2half(v);
        WpcP[i] = *(u16*)&h;
    }
    if (i < PS_P) bpcP[i] = (i < NC_PRED) ? bpc[i] : 0.0f;
    if (i < PS_P * 2 * SC_HALF) {
        int k = i >> 9, n = i & 511;
        int s = n >> 8, nn = n & 255;
        float v = (k < NC_PRED && nn < NC_OBJ) ? Wso[(size_t)s * NC_PRED * NC_OBJ + k * NC_OBJ + nn] : 0.0f;
        __half h = __float2half(v);
        WsoC[i] = *(u16*)&h;
    }
    if (i < 2 * SC_HALF) {
        int s = i >> 8, nn = i & 255;
        bsoC[i] = (nn < NC_OBJ) ? bso[s * NC_OBJ + nn] : 0.0f;
    }
}

// ---------------- tiled small GEMM (fp32, W in smem) ---------------------------
template<int NPAD, int RPT>
__global__ __launch_bounds__(256)
void wgemm_t(const float* __restrict__ A, const float* __restrict__ W,
             const float* __restrict__ bias, int K, int N, int KC, int doRelu,
             float* __restrict__ C,
             const int* __restrict__ rel, int sel, float* __restrict__ sacc) {
    extern __shared__ float sh[];
    float* Ws = sh;
    float* As = sh + (size_t)KC * N;
    const int tid = threadIdx.x;
    const int col = tid % NPAD;
    const int part = tid / NPAD;
    const int rbase = part * RPT;
    const int row0 = blockIdx.x * 32;
    const bool active = col < N;

    float acc[RPT];
    float b = active ? bias[col] : 0.0f;
    #pragma unroll
    for (int r = 0; r < RPT; r++) acc[r] = b;

    for (int k0 = 0; k0 < K; k0 += KC) {
        const int kc = (K - k0 < KC) ? (K - k0) : KC;
        for (int i = tid; i < kc * N; i += 256)
            Ws[i] = W[(size_t)k0 * N + i];
        for (int i = tid; i < 32 * kc; i += 256) {
            int rr = i / kc, kk = i - rr * kc;
            As[rr * KC + kk] = A[(size_t)(row0 + rr) * K + k0 + kk];
        }
        __syncthreads();
        if (active) {
            for (int k = 0; k < kc; k++) {
                float wv = Ws[k * N + col];
                #pragma unroll
                for (int r = 0; r < RPT; r++)
                    acc[r] = fmaf(As[(rbase + r) * KC + k], wv, acc[r]);
            }
        }
        __syncthreads();
    }

    if (active) {
        #pragma unroll
        for (int r = 0; r < RPT; r++) {
            int row = row0 + rbase + r;
            float v = acc[r];
            if (doRelu) v = fmaxf(v, 0.0f);
            if (sacc) {
                int t = rel[row * 2 + sel];
                atomicAdd(&sacc[(size_t)t * N + col], v);
            } else {
                C[(size_t)row * N + col] = v;
            }
        }
    }
}

// ---------------- small utility kernels --------------------------------------
__global__ void zero_kernel(float* p, int n) {
    int i = blockIdx.x * blockDim.x + threadIdx.x;
    if (i < n) p[i] = 0.0f;
}
__global__ void deg_kernel(const int* __restrict__ rel, float* __restrict__ deg) {
    int r = blockIdx.x * blockDim.x + threadIdx.x;
    if (r < N_REL) {
        atomicAdd(&deg[rel[2*r+0]], 1.0f);
        atomicAdd(&deg[N_OBJ + rel[2*r+1]], 1.0f);
    }
}
__global__ void update_o_kernel(const float* __restrict__ of, const float* __restrict__ a0,
                                const float* __restrict__ a1, const float* __restrict__ deg,
                                float* __restrict__ out, u16* __restrict__ oh,
                                int ncols, int apitch, int total) {
    int i = blockIdx.x * blockDim.x + threadIdx.x;
    if (i >= total) return;
    int r = i / ncols;
    int c = i - r * ncols;
    float v = of[i] + 0.5f * (a0[(size_t)r * apitch + c] / (deg[r] + 1e-7f)
                            + a1[(size_t)r * apitch + c] / (deg[N_OBJ + r] + 1e-7f));
    out[i] = v;
    if (oh) {
        __half hv = __float2half(v);
        oh[i] = *(u16*)&hv;
    }
}
__global__ void update_p_kernel(const float* __restrict__ pf, const float* __restrict__ f0,
                                const float* __restrict__ f1, const int* __restrict__ rel,
                                float* __restrict__ out, u16* __restrict__ oh,
                                int ncols, int ppitch, int fpitch, int opitch, int hpitch,
                                int total) {
    int i = blockIdx.x * blockDim.x + threadIdx.x;
    if (i >= total) return;
    int r = i / ncols;
    int c = i - r * ncols;
    int s = rel[2*r+0];
    int o = rel[2*r+1];
    float v = pf[(size_t)r * ppitch + c]
            + 0.5f * (f0[(size_t)s * fpitch + c] + f1[(size_t)o * fpitch + c]) / (1.0f + 1e-7f);
    out[(size_t)r * opitch + c] = v;
    if (oh) {
        __half hv = __float2half(v);
        oh[(size_t)r * hpitch + c] = *(u16*)&hv;
    }
}

// ---------------- host launch helpers -----------------------------------------
static inline void launch_zero(float* p, int n) {
    zero_kernel<<<(n + 255) / 256, 256>>>(p, n);
}
static inline void launch_conv(const float* x, u16* h, int n) {
    conv_kernel<<<(n / 4 + 255) / 256, 256>>>(x, h, n / 4);
}
static inline void launch_gemm_q(const u16* A, const u16* B, const float* b,
                                 int M, int K, int N, int relu,
                                 float* C, u16* Ch, const int* rel, float* sacc, int shalf) {
    dim3 grid(N / 128, M / 128);
    gemm_f16q<<<grid, 128, SMEM_GEMMQ>>>(A, B, b, M, K, N, relu, C, Ch, rel, sacc, shalf);
}
static inline void launch_gemm_h(const u16* A, const u16* B, const float* b,
                                 int M, int K, int N, int relu, float* C, u16* Ch) {
    dim3 grid(N / 128, M / 64);
    gemm_f16h<<<grid, 128, 4 * HST_SZ>>>(A, B, b, M, K, N, relu, C, Ch);
}
static inline void launch_wgemm(const float* A, const float* W, const float* b,
                                int M, int K, int N, int relu,
                                float* C, const int* rel, int sel, float* sacc) {
    int KC = K;
    size_t bytes = ((size_t)KC * N + 32 * KC) * 4;
    if (bytes > 190 * 1024) {
        KC = 256;
        bytes = ((size_t)KC * N + 32 * KC) * 4;
    }
    if (N <= 64)
        wgemm_t<64, 8><<<M / 32, 256, bytes>>>(A, W, b, K, N, KC, relu, C, rel, sel, sacc);
    else
        wgemm_t<256, 32><<<M / 32, 256, bytes>>>(A, W, b, K, N, KC, relu, C, rel, sel, sacc);
}
template <typename T>
static inline T* sym(const void* s) {
    void* p = nullptr;
    cudaGetSymbolAddress(&p, s);
    return (T*)p;
}

extern "C" void kernel_launch(void* const* d_in, const int* in_sizes, int n_in,
                              void* d_out, int out_size) {
    const float* x_obj_raw  = (const float*)d_in[0];
    const float* x_pred_raw = (const float*)d_in[1];
    const int*   rel        = (const int*)  d_in[2];
    const float* oW1 = (const float*)d_in[3],  *ob1 = (const float*)d_in[4];
    const float* oW2 = (const float*)d_in[5],  *ob2 = (const float*)d_in[6];
    const float* rW1 = (const float*)d_in[7],  *rb1 = (const float*)d_in[8];
    const float* rW2 = (const float*)d_in[9],  *rb2 = (const float*)d_in[10];
    const float* Wcf = (const float*)d_in[11], *bcf = (const float*)d_in[12];
    const float* Wso = (const float*)d_in[13], *bso = (const float*)d_in[14];
    const float* Wsr = (const float*)d_in[15], *bsr = (const float*)d_in[16];
    const float* Woc = (const float*)d_in[17], *boc = (const float*)d_in[18];
    const float* Wpc = (const float*)d_in[19], *bpc = (const float*)d_in[20];
    float* out = (float*)d_out;

    cudaFuncSetAttribute(gemm_f16q, cudaFuncAttributeMaxDynamicSharedMemorySize, SMEM_GEMMQ);
    cudaFuncSetAttribute(gemm_f16h, cudaFuncAttributeMaxDynamicSharedMemorySize, 4 * HST_SZ);
    cudaFuncSetAttribute(wgemm_t<64, 8>,   cudaFuncAttributeMaxDynamicSharedMemorySize, 195 * 1024);
    cudaFuncSetAttribute(wgemm_t<256, 32>, cudaFuncAttributeMaxDynamicSharedMemorySize, 195 * 1024);

    float* pfA    = sym<float>(g_pfeatA);
    float* pfB    = sym<float>(g_pfeatB);
    float* ofA    = sym<float>(g_ofeatA);
    float* ofB    = sym<float>(g_ofeatB);
    float* fcoCat = sym<float>(g_fcoCat);
    float* accCat = sym<float>(g_accCat);
    float* osA    = sym<float>(g_osA);
    float* osB    = sym<float>(g_osB);
    float* psA    = sym<float>(g_psA);
    float* psB    = sym<float>(g_psB);
    float* fcs0   = sym<float>(g_fcs0);
    float* fcs1   = sym<float>(g_fcs1);
    float* deg    = sym<float>(g_deg);
    float* bsoC   = sym<float>(g_bsoC);
    float* bpcP   = sym<float>(g_bpcP);

    u16* xo  = sym<u16>(g_xo);
    u16* xp  = sym<u16>(g_xp);
    u16* hob = sym<u16>(g_hob);
    u16* hpr = sym<u16>(g_hpr);
    u16* pfh = sym<u16>(g_pfh);
    u16* psh = sym<u16>(g_psh);
    u16* ofh[2] = { sym<u16>(g_ofh0), sym<u16>(g_ofh1) };
    u16* oW1f = sym<u16>(g_oW1f);
    u16* oW2f = sym<u16>(g_oW2f);
    u16* rW1f = sym<u16>(g_rW1f);
    u16* rW2f = sym<u16>(g_rW2f);
    u16* Wcat01 = sym<u16>(g_Wcat01);
    u16* Wcat23 = sym<u16>(g_Wcat23);
    u16* WsoC = sym<u16>(g_WsoC);
    u16* WpcP = sym<u16>(g_WpcP);

    // ---- degrees + operand conversion / weight packing ----
    launch_zero(deg, 2 * N_OBJ);
    deg_kernel<<<(N_REL + 255) / 256, 256>>>(rel, deg);
    launch_conv(x_obj_raw,  xo, N_OBJ * FEAT);
    launch_conv(x_pred_raw, xp, N_REL * FEAT);
    launch_conv(oW1, oW1f, FEAT * DIM);
    launch_conv(oW2, oW2f, DIM * DIM);
    launch_conv(rW1, rW1f, FEAT * DIM);
    launch_conv(rW2, rW2f, DIM * DIM);
    packW_kernel<<<(DIM * DIM + 255) / 256, 256>>>(Wcf, Wcat01, 0);
    packW_kernel<<<(DIM * DIM + 255) / 256, 256>>>(Wcf, Wcat23, 2);
    packScore_kernel<<<(PS_P * 2 * SC_HALF + 255) / 256, 256>>>(
        Wpc, bpc, Wso, bso, WpcP, bpcP, WsoC, bsoC);

    // ---- embedding MLPs ----
    launch_gemm_h(xo,  oW1f, ob1, N_OBJ, FEAT, DIM, 1, nullptr, hob);
    launch_gemm_h(hob, oW2f, ob2, N_OBJ, DIM,  DIM, 0, ofA,     ofh[0]);
    launch_gemm_q(xp,  rW1f, rb1, N_REL, FEAT, DIM, 1, nullptr, hpr, nullptr, nullptr, 512);
    launch_gemm_q(hpr, rW2f, rb2, N_REL, DIM,  DIM, 0, out,     pfh, nullptr, nullptr, 512);

    // ---- feature-level aGCN (2 steps) ----
    float* of = ofA;  float* ofn = ofB;
    float* pf = out;  float* pfn = pfB;
    int cur = 0;
    for (int st = 0; st < 2; st++) {
        launch_zero(accCat, 2 * N_OBJ * DIM);
        launch_gemm_q(pfh, Wcat01, bcf, N_REL, DIM, 2 * DIM, 1,
                      nullptr, nullptr, rel, accCat, DIM);
        update_o_kernel<<<(N_OBJ * DIM + 255) / 256, 256>>>(
            of, accCat, accCat + N_OBJ * DIM, deg, ofn, ofh[cur ^ 1], DIM, DIM, N_OBJ * DIM);
        launch_gemm_h(ofh[cur], Wcat23, bcf + 2 * DIM, N_OBJ, DIM, 2 * DIM, 1,
                      fcoCat, nullptr);
        update_p_kernel<<<(N_REL * DIM + 255) / 256, 256>>>(
            pf, fcoCat, fcoCat + DIM, rel, pfn, pfh, DIM, DIM, 2 * DIM, DIM, DIM, N_REL * DIM);
        float* t = of; of = ofn; ofn = t;
        pf = pfn; pfn = (st == 0) ? pfA : pfB;
        cur ^= 1;
    }

    // ---- classifiers ----
    launch_wgemm(of, Woc, boc, N_OBJ, DIM, NC_OBJ, 0, osA, nullptr, 0, nullptr);
    launch_gemm_q(pfh, WpcP, bpcP, N_REL, DIM, PS_P, 0, psA, psh, nullptr, nullptr, 512);

    // ---- score-level aGCN (2 steps; final writes straight into out) ----
    float* outO = out + (size_t)N_REL * DIM;
    float* outP = out + (size_t)N_REL * DIM + N_OBJ * NC_OBJ;
    float* os = osA;
    float* ps = psA;
    for (int st = 0; st < 2; st++) {
        float* osn = (st == 0) ? osB : outO;
        launch_zero(accCat, 2 * N_OBJ * SC_HALF);
        launch_gemm_q(psh, WsoC, bsoC, N_REL, PS_P, 2 * SC_HALF, 1,
                      nullptr, nullptr, rel, accCat, SC_HALF);
        update_o_kernel<<<(N_OBJ * NC_OBJ + 255) / 256, 256>>>(
            os, accCat, accCat + N_OBJ * SC_HALF, deg, osn, nullptr,
            NC_OBJ, SC_HALF, N_OBJ * NC_OBJ);
        launch_wgemm(os, Wsr + 0 * NC_OBJ * NC_PRED, bsr + 0 * NC_PRED,
                     N_OBJ, NC_OBJ, NC_PRED, 1, fcs0, nullptr, 0, nullptr);
        launch_wgemm(os, Wsr + 1 * NC_OBJ * NC_PRED, bsr + 1 * NC_PRED,
                     N_OBJ, NC_OBJ, NC_PRED, 1, fcs1, nullptr, 0, nullptr);
        if (st == 0) {
            update_p_kernel<<<(N_REL * NC_PRED + 255) / 256, 256>>>(
                ps, fcs0, fcs1, rel, psB, psh,
                NC_PRED, PS_P, NC_PRED, PS_P, PS_P, N_REL * NC_PRED);
            ps = psB;
        } else {
            update_p_kernel<<<(N_REL * NC_PRED + 255) / 256, 256>>>(
                ps, fcs0, fcs1, rel, outP, nullptr,
                NC_PRED, PS_P, NC_PRED, NC_PRED, PS_P, N_REL * NC_PRED);
        }
        os = osn;
    }
}

// round 15
// speedup vs baseline: 1.0784x; 1.0784x over previous
#include <cuda_runtime.h>
#include <cuda_fp16.h>
#include <cstdint>
#include <math.h>

#define N_OBJ   2048
#define N_REL   32768
#define FEAT    2048
#define DIM     512
#define NC_OBJ  151
#define NC_PRED 51
#define PS_P    128      // padded pitch for pred scores
#define SC_HALF 256      // score scatter half width
#define SR_N    (2*NC_PRED)   // fused Wsr output width = 102

typedef unsigned short u16;

// ---------------- fp32 scratch ------------------------------------------------
__device__ __align__(128) float g_pfeatA[N_REL*DIM];
__device__ __align__(128) float g_pfeatB[N_REL*DIM];
__device__ __align__(128) float g_ofeatA[N_OBJ*DIM];
__device__ __align__(128) float g_ofeatB[N_OBJ*DIM];
__device__ __align__(128) float g_fcoCat[N_OBJ*2*DIM];
__device__ __align__(128) float g_accCat[2*N_OBJ*DIM];
__device__ __align__(128) float g_osA   [N_OBJ*NC_OBJ];
__device__ __align__(128) float g_osB   [N_OBJ*NC_OBJ];
__device__ __align__(128) float g_psA   [N_REL*PS_P];
__device__ __align__(128) float g_psB   [N_REL*PS_P];
__device__ __align__(128) float g_fcsC  [N_OBJ*SR_N];
__device__ __align__(128) float g_deg   [2*N_OBJ];
__device__ __align__(128) float g_rdeg  [2*N_OBJ];
__device__ __align__(128) float g_bsoC  [2*SC_HALF];
__device__ __align__(128) float g_bpcP  [PS_P];
__device__ __align__(128) float g_WsrC  [NC_OBJ*SR_N];

// ---------------- fp16 operand buffers ----------------------------------------
__device__ __align__(128) u16 g_xo  [N_OBJ*FEAT];
__device__ __align__(128) u16 g_xp  [N_REL*FEAT];
__device__ __align__(128) u16 g_hob [N_OBJ*DIM];
__device__ __align__(128) u16 g_hpr [N_REL*DIM];
__device__ __align__(128) u16 g_pfh [N_REL*DIM];
__device__ __align__(128) u16 g_psh [N_REL*PS_P];
__device__ __align__(128) u16 g_ofh0[N_OBJ*DIM];
__device__ __align__(128) u16 g_ofh1[N_OBJ*DIM];
__device__ __align__(128) u16 g_oW1f[FEAT*DIM];
__device__ __align__(128) u16 g_oW2f[DIM*DIM];
__device__ __align__(128) u16 g_rW1f[FEAT*DIM];
__device__ __align__(128) u16 g_rW2f[DIM*DIM];
__device__ __align__(128) u16 g_Wcat01[DIM*2*DIM];
__device__ __align__(128) u16 g_Wcat23[DIM*2*DIM];
__device__ __align__(128) u16 g_WsoC[PS_P*2*SC_HALF];
__device__ __align__(128) u16 g_WpcP[DIM*PS_P];

// ---------------- helpers ------------------------------------------------------
__device__ __forceinline__ uint32_t smem_u32(const void* p) {
    uint32_t a;
    asm("{ .reg .u64 t; cvta.to.shared.u64 t, %1; cvt.u32.u64 %0, t; }" : "=r"(a) : "l"(p));
    return a;
}
__device__ __forceinline__ uint32_t pack_h2(float x, float y) {
    uint32_t d;
    asm("cvt.rn.f16x2.f32 %0, %1, %2;" : "=r"(d) : "f"(y), "f"(x));
    return d;
}
__device__ __forceinline__ void ldsm_x4(uint32_t* r, uint32_t addr) {
    asm volatile("ldmatrix.sync.aligned.m8n8.x4.shared.b16 {%0,%1,%2,%3}, [%4];"
                 : "=r"(r[0]), "=r"(r[1]), "=r"(r[2]), "=r"(r[3]) : "r"(addr));
}
__device__ __forceinline__ void ldsm_x4_t(uint32_t* r, uint32_t addr) {
    asm volatile("ldmatrix.sync.aligned.m8n8.x4.trans.shared.b16 {%0,%1,%2,%3}, [%4];"
                 : "=r"(r[0]), "=r"(r[1]), "=r"(r[2]), "=r"(r[3]) : "r"(addr));
}
__device__ __forceinline__ void mma16816(float* c, const uint32_t* a, uint32_t b0, uint32_t b1) {
    asm volatile("mma.sync.aligned.m16n8k16.row.col.f32.f16.f16.f32 "
                 "{%0,%1,%2,%3}, {%4,%5,%6,%7}, {%8,%9}, {%0,%1,%2,%3};"
                 : "+f"(c[0]), "+f"(c[1]), "+f"(c[2]), "+f"(c[3])
                 : "r"(a[0]), "r"(a[1]), "r"(a[2]), "r"(a[3]), "r"(b0), "r"(b1));
}
__device__ __forceinline__ void cp16(uint32_t dst, const void* src) {
    asm volatile("cp.async.cg.shared.global [%0], [%1], 16;" :: "r"(dst), "l"(src) : "memory");
}
#define CP_COMMIT() asm volatile("cp.async.commit_group;" ::: "memory")
#define CP_WAIT2()  asm volatile("cp.async.wait_group 2;" ::: "memory")

#define APITCH 80
#define BPITCH 272
#define ST_A   0
#define ST_B   10240
#define ST_SZ  18944
#define SMEM_GEMM (4*ST_SZ)

// epilogue helper shared by tensor kernels
__device__ __forceinline__ void epi_quad(
    float* a, int r0, int r1, int c, int N, int doRelu,
    const float* bias, float* C, u16* Ch,
    float* saccB, int t0, int t1, int shalf, int side) {
    float b0 = bias[c], b1 = bias[c + 1];
    float v0 = a[0] + b0, v1 = a[1] + b1, v2 = a[2] + b0, v3 = a[3] + b1;
    if (doRelu) {
        v0 = fmaxf(v0, 0.0f); v1 = fmaxf(v1, 0.0f);
        v2 = fmaxf(v2, 0.0f); v3 = fmaxf(v3, 0.0f);
    }
    if (saccB) {
        const int col = c - side * shalf;
        atomicAdd(&saccB[(size_t)t0 * shalf + col],     v0);
        atomicAdd(&saccB[(size_t)t0 * shalf + col + 1], v1);
        atomicAdd(&saccB[(size_t)t1 * shalf + col],     v2);
        atomicAdd(&saccB[(size_t)t1 * shalf + col + 1], v3);
    } else {
        if (C) {
            *(float2*)(C + (size_t)r0 * N + c) = make_float2(v0, v1);
            *(float2*)(C + (size_t)r1 * N + c) = make_float2(v2, v3);
        }
        if (Ch) {
            *(uint32_t*)(Ch + (size_t)r0 * N + c) = pack_h2(v0, v1);
            *(uint32_t*)(Ch + (size_t)r1 * N + c) = pack_h2(v2, v3);
        }
    }
}

// ================== QUAD GEMM: CTA 128x128, 4 warps 64x64, K-tile 32, 4-stage ===
// (R13-proven config.) If sacc: fused dual scatter [2][N_OBJ][shalf], side=n0/shalf.
__global__ __launch_bounds__(128, 2)
void gemm_f16q(const u16* __restrict__ A, const u16* __restrict__ B,
               const float* __restrict__ bias, int M, int K, int N, int doRelu,
               float* __restrict__ C, u16* __restrict__ Ch,
               const int* __restrict__ rel, float* __restrict__ sacc, int shalf) {
    extern __shared__ __align__(128) char smem[];
    const uint32_t sb = smem_u32(smem);
    const int tid = threadIdx.x;
    const int lane = tid & 31;
    const int w = tid >> 5;
    const int warp_m = (w & 1) * 64;
    const int warp_n = (w >> 1) * 64;
    const int m0 = blockIdx.y * 128;
    const int n0 = blockIdx.x * 128;
    const int KT = K >> 5;

    float acc[32][4];
    #pragma unroll
    for (int i = 0; i < 32; i++)
        #pragma unroll
        for (int j = 0; j < 4; j++) acc[i][j] = 0.0f;

    auto issue = [&](int kt) {
        const uint32_t st = sb + (kt & 3) * ST_SZ;
        #pragma unroll
        for (int i = 0; i < 4; i++) {
            int idx = i * 128 + tid;
            int arow = idx >> 2, ac = idx & 3;
            size_t ga = (size_t)(m0 + arow) * K + kt * 32 + ac * 8;
            cp16(st + ST_A + (uint32_t)(arow * APITCH + ac * 16), A + ga);
        }
        #pragma unroll
        for (int i = 0; i < 4; i++) {
            int idx = i * 128 + tid;
            int brow = idx >> 4, bc = idx & 15;
            size_t gb = (size_t)(kt * 32 + brow) * N + n0 + bc * 8;
            cp16(st + ST_B + (uint32_t)(brow * BPITCH + bc * 16), B + gb);
        }
    };

    issue(0); CP_COMMIT();
    issue(1); CP_COMMIT();
    issue(2); CP_COMMIT();

    for (int kt = 0; kt < KT; kt++) {
        CP_WAIT2();
        __syncthreads();
        if (kt + 3 < KT) issue(kt + 3);
        CP_COMMIT();

        const uint32_t st = sb + (kt & 3) * ST_SZ;
        #pragma unroll
        for (int ks = 0; ks < 2; ks++) {
            uint32_t ah[4][4];
            const uint32_t a_off = (uint32_t)((warp_m + (lane & 15)) * APITCH
                                              + ks * 32 + (lane >> 4) * 16);
            #pragma unroll
            for (int mi = 0; mi < 4; mi++)
                ldsm_x4(ah[mi], st + ST_A + a_off + mi * 16 * APITCH);
            const uint32_t b_off = (uint32_t)((ks * 16 + (lane & 15)) * BPITCH
                                              + (warp_n + (lane >> 4) * 8) * 2);
            #pragma unroll
            for (int np = 0; np < 4; np++) {
                uint32_t bh[4];
                ldsm_x4_t(bh, st + ST_B + b_off + np * 32);
                #pragma unroll
                for (int mi = 0; mi < 4; mi++) {
                    #pragma unroll
                    for (int j = 0; j < 2; j++)
                        mma16816(acc[mi * 8 + np * 2 + j], ah[mi], bh[2*j], bh[2*j+1]);
                }
            }
        }
    }

    const int g = lane >> 2, tig = lane & 3;
    float* saccB = nullptr;
    int side = 0;
    if (sacc) { side = n0 / shalf; saccB = sacc + (size_t)side * N_OBJ * shalf; }
    #pragma unroll
    for (int mi = 0; mi < 4; mi++) {
        const int r0 = m0 + warp_m + mi * 16 + g;
        const int r1 = r0 + 8;
        int t0 = 0, t1 = 0;
        if (sacc) { t0 = rel[r0 * 2 + side]; t1 = rel[r1 * 2 + side]; }
        #pragma unroll
        for (int ni = 0; ni < 8; ni++) {
            const int c = n0 + warp_n + ni * 8 + tig * 2;
            epi_quad(acc[mi * 8 + ni], r0, r1, c, N, doRelu, bias, C, Ch,
                     saccB, t0, t1, shalf, side);
        }
    }
}

// ================== HALF-M GEMM: CTA 64x128, 4 warps 32x64, 4 CTA/SM ===========
#define HST_A 0
#define HST_B 5120
#define HST_SZ 13824

__global__ __launch_bounds__(128, 4)
void gemm_f16h(const u16* __restrict__ A, const u16* __restrict__ B,
               const float* __restrict__ bias, int M, int K, int N, int doRelu,
               float* __restrict__ C, u16* __restrict__ Ch) {
    extern __shared__ __align__(128) char smem[];
    const uint32_t sb = smem_u32(smem);
    const int tid = threadIdx.x;
    const int lane = tid & 31;
    const int w = tid >> 5;
    const int warp_m = (w & 1) * 32;
    const int warp_n = (w >> 1) * 64;
    const int m0 = blockIdx.y * 64;
    const int n0 = blockIdx.x * 128;
    const int KT = K >> 5;

    float acc[16][4];
    #pragma unroll
    for (int i = 0; i < 16; i++)
        #pragma unroll
        for (int j = 0; j < 4; j++) acc[i][j] = 0.0f;

    auto issue = [&](int kt) {
        const uint32_t st = sb + (kt & 3) * HST_SZ;
        #pragma unroll
        for (int i = 0; i < 2; i++) {
            int idx = i * 128 + tid;
            int arow = idx >> 2, ac = idx & 3;
            size_t ga = (size_t)(m0 + arow) * K + kt * 32 + ac * 8;
            cp16(st + HST_A + (uint32_t)(arow * APITCH + ac * 16), A + ga);
        }
        #pragma unroll
        for (int i = 0; i < 4; i++) {
            int idx = i * 128 + tid;
            int brow = idx >> 4, bc = idx & 15;
            size_t gb = (size_t)(kt * 32 + brow) * N + n0 + bc * 8;
            cp16(st + HST_B + (uint32_t)(brow * BPITCH + bc * 16), B + gb);
        }
    };

    issue(0); CP_COMMIT();
    issue(1); CP_COMMIT();
    issue(2); CP_COMMIT();

    for (int kt = 0; kt < KT; kt++) {
        CP_WAIT2();
        __syncthreads();
        if (kt + 3 < KT) issue(kt + 3);
        CP_COMMIT();

        const uint32_t st = sb + (kt & 3) * HST_SZ;
        #pragma unroll
        for (int ks = 0; ks < 2; ks++) {
            uint32_t ah[2][4];
            const uint32_t a_off = (uint32_t)((warp_m + (lane & 15)) * APITCH
                                              + ks * 32 + (lane >> 4) * 16);
            #pragma unroll
            for (int mi = 0; mi < 2; mi++)
                ldsm_x4(ah[mi], st + HST_A + a_off + mi * 16 * APITCH);
            const uint32_t b_off = (uint32_t)((ks * 16 + (lane & 15)) * BPITCH
                                              + (warp_n + (lane >> 4) * 8) * 2);
            #pragma unroll
            for (int np = 0; np < 4; np++) {
                uint32_t bh[4];
                ldsm_x4_t(bh, st + HST_B + b_off + np * 32);
                #pragma unroll
                for (int mi = 0; mi < 2; mi++) {
                    #pragma unroll
                    for (int j = 0; j < 2; j++)
                        mma16816(acc[mi * 8 + np * 2 + j], ah[mi], bh[2*j], bh[2*j+1]);
                }
            }
        }
    }

    const int g = lane >> 2, tig = lane & 3;
    #pragma unroll
    for (int mi = 0; mi < 2; mi++) {
        const int r0 = m0 + warp_m + mi * 16 + g;
        const int r1 = r0 + 8;
        #pragma unroll
        for (int ni = 0; ni < 8; ni++) {
            const int c = n0 + warp_n + ni * 8 + tig * 2;
            epi_quad(acc[mi * 8 + ni], r0, r1, c, N, doRelu, bias, C, Ch,
                     nullptr, 0, 0, 0, 0);
        }
    }
}

// ---------------- converters / packers ------------------------------------------
__global__ void conv_kernel(const float* __restrict__ x, u16* __restrict__ h, int n4) {
    int i = blockIdx.x * blockDim.x + threadIdx.x;
    if (i >= n4) return;
    float4 v = *(const float4*)(x + i * 4);
    uint2 o;
    o.x = pack_h2(v.x, v.y);
    o.y = pack_h2(v.z, v.w);
    *(uint2*)(h + i * 4) = o;
}
__global__ void packW_kernel(const float* __restrict__ W, u16* __restrict__ out, int base) {
    int i = blockIdx.x * blockDim.x + threadIdx.x;
    if (i >= DIM * DIM) return;
    int idx = i * 2;
    int k = idx >> 10, c = idx & 1023;
    int s = c >> 9, n = c & 511;
    const float* src = W + ((size_t)(base + s)) * DIM * DIM + (size_t)k * DIM + n;
    *(uint32_t*)(out + idx) = pack_h2(src[0], src[1]);
}
__global__ void packScore_kernel(const float* __restrict__ Wpc, const float* __restrict__ bpc,
                                 const float* __restrict__ Wso, const float* __restrict__ bso,
                                 const float* __restrict__ Wsr,
                                 u16* __restrict__ WpcP, float* __restrict__ bpcP,
                                 u16* __restrict__ WsoC, float* __restrict__ bsoC,
                                 float* __restrict__ WsrC) {
    int i = blockIdx.x * blockDim.x + threadIdx.x;
    if (i < DIM * PS_P) {
        int k = i >> 7, n = i & 127;
        float v = (n < NC_PRED) ? Wpc[k * NC_PRED + n] : 0.0f;
        __half h = __float2half(v);
        WpcP[i] = *(u16*)&h;
    }
    if (i < PS_P) bpcP[i] = (i < NC_PRED) ? bpc[i] : 0.0f;
    if (i < PS_P * 2 * SC_HALF) {
        int k = i >> 9, n = i & 511;
        int s = n >> 8, nn = n & 255;
        float v = (k < NC_PRED && nn < NC_OBJ) ? Wso[(size_t)s * NC_PRED * NC_OBJ + k * NC_OBJ + nn] : 0.0f;
        __half h = __float2half(v);
        WsoC[i] = *(u16*)&h;
    }
    if (i < 2 * SC_HALF) {
        int s = i >> 8, nn = i & 255;
        bsoC[i] = (nn < NC_OBJ) ? bso[s * NC_OBJ + nn] : 0.0f;
    }
    // WsrC [151][102]: col<51 -> Wsr[0][k][col], else Wsr[1][k][col-51]
    if (i < NC_OBJ * SR_N) {
        int k = i / SR_N, c = i - (i / SR_N) * SR_N;
        int s = (c >= NC_PRED) ? 1 : 0;
        int cc = c - s * NC_PRED;
        WsrC[i] = Wsr[(size_t)s * NC_OBJ * NC_PRED + k * NC_PRED + cc];
    }
}

// ---------------- tiled small GEMM (fp32, W in smem) ---------------------------
template<int NPAD, int RPT>
__global__ __launch_bounds__(256)
void wgemm_t(const float* __restrict__ A, const float* __restrict__ W,
             const float* __restrict__ bias, int K, int N, int KC, int doRelu,
             float* __restrict__ C,
             const int* __restrict__ rel, int sel, float* __restrict__ sacc) {
    extern __shared__ float sh[];
    float* Ws = sh;
    float* As = sh + (size_t)KC * N;
    const int tid = threadIdx.x;
    const int col = tid % NPAD;
    const int part = tid / NPAD;
    const int rbase = part * RPT;
    const int row0 = blockIdx.x * 32;
    const bool active = col < N;

    float acc[RPT];
    float b = active ? bias[col] : 0.0f;
    #pragma unroll
    for (int r = 0; r < RPT; r++) acc[r] = b;

    for (int k0 = 0; k0 < K; k0 += KC) {
        const int kc = (K - k0 < KC) ? (K - k0) : KC;
        for (int i = tid; i < kc * N; i += 256)
            Ws[i] = W[(size_t)k0 * N + i];
        for (int i = tid; i < 32 * kc; i += 256) {
            int rr = i / kc, kk = i - rr * kc;
            As[rr * KC + kk] = A[(size_t)(row0 + rr) * K + k0 + kk];
        }
        __syncthreads();
        if (active) {
            for (int k = 0; k < kc; k++) {
                float wv = Ws[k * N + col];
                #pragma unroll
                for (int r = 0; r < RPT; r++)
                    acc[r] = fmaf(As[(rbase + r) * KC + k], wv, acc[r]);
            }
        }
        __syncthreads();
    }

    if (active) {
        #pragma unroll
        for (int r = 0; r < RPT; r++) {
            int row = row0 + rbase + r;
            float v = acc[r];
            if (doRelu) v = fmaxf(v, 0.0f);
            if (sacc) {
                int t = rel[row * 2 + sel];
                atomicAdd(&sacc[(size_t)t * N + col], v);
            } else {
                C[(size_t)row * N + col] = v;
            }
        }
    }
}

// ---------------- small utility kernels --------------------------------------
__global__ void zero_kernel(float* p, int n) {
    int i = blockIdx.x * blockDim.x + threadIdx.x;
    if (i < n) p[i] = 0.0f;
}
__global__ void deg_kernel(const int* __restrict__ rel, float* __restrict__ deg) {
    int r = blockIdx.x * blockDim.x + threadIdx.x;
    if (r < N_REL) {
        atomicAdd(&deg[rel[2*r+0]], 1.0f);
        atomicAdd(&deg[N_OBJ + rel[2*r+1]], 1.0f);
    }
}
__global__ void rdeg_kernel(const float* __restrict__ deg, float* __restrict__ rdeg, int n) {
    int i = blockIdx.x * blockDim.x + threadIdx.x;
    if (i < n) rdeg[i] = 1.0f / (deg[i] + 1e-7f);
}
// new_o = of + 0.5*(a0*rdegS + a1*rdegO)
__global__ void update_o_kernel(const float* __restrict__ of, const float* __restrict__ a0,
                                const float* __restrict__ a1, const float* __restrict__ rdeg,
                                float* __restrict__ out, u16* __restrict__ oh,
                                int ncols, int apitch, int total) {
    int i = blockIdx.x * blockDim.x + threadIdx.x;
    if (i >= total) return;
    int r = i / ncols;
    int c = i - r * ncols;
    float v = of[i] + 0.5f * (a0[(size_t)r * apitch + c] * rdeg[r]
                            + a1[(size_t)r * apitch + c] * rdeg[N_OBJ + r]);
    out[i] = v;
    if (oh) {
        __half hv = __float2half(v);
        oh[i] = *(u16*)&hv;
    }
}
__global__ void update_p_kernel(const float* __restrict__ pf, const float* __restrict__ f0,
                                const float* __restrict__ f1, const int* __restrict__ rel,
                                float* __restrict__ out, u16* __restrict__ oh,
                                int ncols, int ppitch, int fpitch, int opitch, int hpitch,
                                int total) {
    int i = blockIdx.x * blockDim.x + threadIdx.x;
    if (i >= total) return;
    int r = i / ncols;
    int c = i - r * ncols;
    int s = rel[2*r+0];
    int o = rel[2*r+1];
    float v = pf[(size_t)r * ppitch + c]
            + 0.5f * (f0[(size_t)s * fpitch + c] + f1[(size_t)o * fpitch + c]) / (1.0f + 1e-7f);
    out[(size_t)r * opitch + c] = v;
    if (oh) {
        __half hv = __float2half(v);
        oh[(size_t)r * hpitch + c] = *(u16*)&hv;
    }
}

// ---------------- host launch helpers -----------------------------------------
static inline void launch_zero(float* p, int n) {
    zero_kernel<<<(n + 255) / 256, 256>>>(p, n);
}
static inline void launch_conv(const float* x, u16* h, int n) {
    conv_kernel<<<(n / 4 + 255) / 256, 256>>>(x, h, n / 4);
}
static inline void launch_gemm_q(const u16* A, const u16* B, const float* b,
                                 int M, int K, int N, int relu,
                                 float* C, u16* Ch, const int* rel, float* sacc, int shalf) {
    dim3 grid(N / 128, M / 128);
    gemm_f16q<<<grid, 128, SMEM_GEMM>>>(A, B, b, M, K, N, relu, C, Ch, rel, sacc, shalf);
}
static inline void launch_gemm_h(const u16* A, const u16* B, const float* b,
                                 int M, int K, int N, int relu, float* C, u16* Ch) {
    dim3 grid(N / 128, M / 64);
    gemm_f16h<<<grid, 128, 4 * HST_SZ>>>(A, B, b, M, K, N, relu, C, Ch);
}
template<int NPAD, int RPT>
static inline void launch_wgemm_t(const float* A, const float* W, const float* b,
                                  int M, int K, int N, int relu,
                                  float* C, const int* rel, int sel, float* sacc) {
    int KC = K;
    size_t bytes = ((size_t)KC * N + 32 * KC) * 4;
    if (bytes > 190 * 1024) {
        KC = 256;
        bytes = ((size_t)KC * N + 32 * KC) * 4;
    }
    wgemm_t<NPAD, RPT><<<M / 32, 256, bytes>>>(A, W, b, K, N, KC, relu, C, rel, sel, sacc);
}
template <typename T>
static inline T* sym(const void* s) {
    void* p = nullptr;
    cudaGetSymbolAddress(&p, s);
    return (T*)p;
}

extern "C" void kernel_launch(void* const* d_in, const int* in_sizes, int n_in,
                              void* d_out, int out_size) {
    const float* x_obj_raw  = (const float*)d_in[0];
    const float* x_pred_raw = (const float*)d_in[1];
    const int*   rel        = (const int*)  d_in[2];
    const float* oW1 = (const float*)d_in[3],  *ob1 = (const float*)d_in[4];
    const float* oW2 = (const float*)d_in[5],  *ob2 = (const float*)d_in[6];
    const float* rW1 = (const float*)d_in[7],  *rb1 = (const float*)d_in[8];
    const float* rW2 = (const float*)d_in[9],  *rb2 = (const float*)d_in[10];
    const float* Wcf = (const float*)d_in[11], *bcf = (const float*)d_in[12];
    const float* Wso = (const float*)d_in[13], *bso = (const float*)d_in[14];
    const float* Wsr = (const float*)d_in[15], *bsr = (const float*)d_in[16];
    const float* Woc = (const float*)d_in[17], *boc = (const float*)d_in[18];
    const float* Wpc = (const float*)d_in[19], *bpc = (const float*)d_in[20];
    float* out = (float*)d_out;

    cudaFuncSetAttribute(gemm_f16q, cudaFuncAttributeMaxDynamicSharedMemorySize, SMEM_GEMM);
    cudaFuncSetAttribute(gemm_f16h, cudaFuncAttributeMaxDynamicSharedMemorySize, 4 * HST_SZ);
    cudaFuncSetAttribute(wgemm_t<256, 32>, cudaFuncAttributeMaxDynamicSharedMemorySize, 195 * 1024);
    cudaFuncSetAttribute(wgemm_t<128, 16>, cudaFuncAttributeMaxDynamicSharedMemorySize, 195 * 1024);

    float* pfA    = sym<float>(g_pfeatA);
    float* pfB    = sym<float>(g_pfeatB);
    float* ofA    = sym<float>(g_ofeatA);
    float* ofB    = sym<float>(g_ofeatB);
    float* fcoCat = sym<float>(g_fcoCat);
    float* accCat = sym<float>(g_accCat);
    float* osA    = sym<float>(g_osA);
    float* osB    = sym<float>(g_osB);
    float* psA    = sym<float>(g_psA);
    float* psB    = sym<float>(g_psB);
    float* fcsC   = sym<float>(g_fcsC);
    float* deg    = sym<float>(g_deg);
    float* rdeg   = sym<float>(g_rdeg);
    float* bsoC   = sym<float>(g_bsoC);
    float* bpcP   = sym<float>(g_bpcP);
    float* WsrC   = sym<float>(g_WsrC);

    u16* xo  = sym<u16>(g_xo);
    u16* xp  = sym<u16>(g_xp);
    u16* hob = sym<u16>(g_hob);
    u16* hpr = sym<u16>(g_hpr);
    u16* pfh = sym<u16>(g_pfh);
    u16* psh = sym<u16>(g_psh);
    u16* ofh[2] = { sym<u16>(g_ofh0), sym<u16>(g_ofh1) };
    u16* oW1f = sym<u16>(g_oW1f);
    u16* oW2f = sym<u16>(g_oW2f);
    u16* rW1f = sym<u16>(g_rW1f);
    u16* rW2f = sym<u16>(g_rW2f);
    u16* Wcat01 = sym<u16>(g_Wcat01);
    u16* Wcat23 = sym<u16>(g_Wcat23);
    u16* WsoC = sym<u16>(g_WsoC);
    u16* WpcP = sym<u16>(g_WpcP);

    // ---- degrees + operand conversion / weight packing ----
    launch_zero(deg, 2 * N_OBJ);
    deg_kernel<<<(N_REL + 255) / 256, 256>>>(rel, deg);
    rdeg_kernel<<<(2 * N_OBJ + 255) / 256, 256>>>(deg, rdeg, 2 * N_OBJ);
    launch_conv(x_obj_raw,  xo, N_OBJ * FEAT);
    launch_conv(x_pred_raw, xp, N_REL * FEAT);
    launch_conv(oW1, oW1f, FEAT * DIM);
    launch_conv(oW2, oW2f, DIM * DIM);
    launch_conv(rW1, rW1f, FEAT * DIM);
    launch_conv(rW2, rW2f, DIM * DIM);
    packW_kernel<<<(DIM * DIM + 255) / 256, 256>>>(Wcf, Wcat01, 0);
    packW_kernel<<<(DIM * DIM + 255) / 256, 256>>>(Wcf, Wcat23, 2);
    packScore_kernel<<<(PS_P * 2 * SC_HALF + 255) / 256, 256>>>(
        Wpc, bpc, Wso, bso, Wsr, WpcP, bpcP, WsoC, bsoC, WsrC);

    // ---- embedding MLPs ----
    launch_gemm_h(xo,  oW1f, ob1, N_OBJ, FEAT, DIM, 1, nullptr, hob);
    launch_gemm_h(hob, oW2f, ob2, N_OBJ, DIM,  DIM, 0, ofA,     ofh[0]);
    launch_gemm_q(xp,  rW1f, rb1, N_REL, FEAT, DIM, 1, nullptr, hpr, nullptr, nullptr, 512);
    launch_gemm_q(hpr, rW2f, rb2, N_REL, DIM,  DIM, 0, out,     pfh, nullptr, nullptr, 512);

    // ---- feature-level aGCN (2 steps) ----
    float* of = ofA;  float* ofn = ofB;
    float* pf = out;  float* pfn = pfB;
    int cur = 0;
    for (int st = 0; st < 2; st++) {
        launch_zero(accCat, 2 * N_OBJ * DIM);
        launch_gemm_q(pfh, Wcat01, bcf, N_REL, DIM, 2 * DIM, 1,
                      nullptr, nullptr, rel, accCat, DIM);
        update_o_kernel<<<(N_OBJ * DIM + 255) / 256, 256>>>(
            of, accCat, accCat + N_OBJ * DIM, rdeg, ofn, ofh[cur ^ 1], DIM, DIM, N_OBJ * DIM);
        launch_gemm_h(ofh[cur], Wcat23, bcf + 2 * DIM, N_OBJ, DIM, 2 * DIM, 1,
                      fcoCat, nullptr);
        update_p_kernel<<<(N_REL * DIM + 255) / 256, 256>>>(
            pf, fcoCat, fcoCat + DIM, rel, pfn, pfh, DIM, DIM, 2 * DIM, DIM, DIM, N_REL * DIM);
        float* t = of; of = ofn; ofn = t;
        pf = pfn; pfn = (st == 0) ? pfA : pfB;
        cur ^= 1;
    }

    // ---- classifiers ----
    launch_wgemm_t<256, 32>(of, Woc, boc, N_OBJ, DIM, NC_OBJ, 0, osA, nullptr, 0, nullptr);
    launch_gemm_q(pfh, WpcP, bpcP, N_REL, DIM, PS_P, 0, psA, psh, nullptr, nullptr, 512);

    // ---- score-level aGCN (2 steps; final writes straight into out) ----
    float* outO = out + (size_t)N_REL * DIM;
    float* outP = out + (size_t)N_REL * DIM + N_OBJ * NC_OBJ;
    float* os = osA;
    float* ps = psA;
    for (int st = 0; st < 2; st++) {
        float* osn = (st == 0) ? osB : outO;
        launch_zero(accCat, 2 * N_OBJ * SC_HALF);
        launch_gemm_q(psh, WsoC, bsoC, N_REL, PS_P, 2 * SC_HALF, 1,
                      nullptr, nullptr, rel, accCat, SC_HALF);
        update_o_kernel<<<(N_OBJ * NC_OBJ + 255) / 256, 256>>>(
            os, accCat, accCat + N_OBJ * SC_HALF, rdeg, osn, nullptr,
            NC_OBJ, SC_HALF, N_OBJ * NC_OBJ);
        // fused Wsr gather: relu(os @ WsrC + bsr) -> fcsC [2048][102]
        launch_wgemm_t<128, 16>(os, WsrC, bsr, N_OBJ, NC_OBJ, SR_N, 1,
                                fcsC, nullptr, 0, nullptr);
        if (st == 0) {
            update_p_kernel<<<(N_REL * NC_PRED + 255) / 256, 256>>>(
                ps, fcsC, fcsC + NC_PRED, rel, psB, psh,
                NC_PRED, PS_P, SR_N, PS_P, PS_P, N_REL * NC_PRED);
            ps = psB;
        } else {
            update_p_kernel<<<(N_REL * NC_PRED + 255) / 256, 256>>>(
                ps, fcsC, fcsC + NC_PRED, rel, outP, nullptr,
                NC_PRED, PS_P, SR_N, NC_PRED, PS_P, N_REL * NC_PRED);
        }
        os = osn;
    }
}

// round 17
// speedup vs baseline: 1.1847x; 1.0986x over previous
#include <cuda_runtime.h>
#include <cuda_fp16.h>
#include <cstdint>
#include <math.h>

#define N_OBJ   2048
#define N_REL   32768
#define FEAT    2048
#define DIM     512
#define NC_OBJ  151
#define NC_PRED 51
#define PS_P    128
#define SC_HALF 256
#define SR_N    (2*NC_PRED)

typedef unsigned short u16;

// ---------------- fp32 scratch ------------------------------------------------
__device__ __align__(128) float g_pfeatA[N_REL*DIM];
__device__ __align__(128) float g_pfeatB[N_REL*DIM];
__device__ __align__(128) float g_ofeatA[N_OBJ*DIM];
__device__ __align__(128) float g_ofeatB[N_OBJ*DIM];
__device__ __align__(128) float g_fcoCat [N_OBJ*2*DIM];
__device__ __align__(128) float g_fcoCat2[N_OBJ*2*DIM];   // second buffer: kills the R16 race
__device__ __align__(128) float g_accCat[2*N_OBJ*DIM];
__device__ __align__(128) float g_osA   [N_OBJ*NC_OBJ];
__device__ __align__(128) float g_osB   [N_OBJ*NC_OBJ];
__device__ __align__(128) float g_psA   [N_REL*PS_P];
__device__ __align__(128) float g_psB   [N_REL*PS_P];
__device__ __align__(128) float g_fcsC  [N_OBJ*SR_N];
__device__ __align__(128) float g_fcsC2 [N_OBJ*SR_N];     // second buffer for score step 1
__device__ __align__(128) float g_deg   [2*N_OBJ];
__device__ __align__(128) float g_rdeg  [2*N_OBJ];
__device__ __align__(128) float g_bsoC  [2*SC_HALF];
__device__ __align__(128) float g_bpcP  [PS_P];
__device__ __align__(128) float g_WsrC  [NC_OBJ*SR_N];

// ---------------- fp16 operand buffers ----------------------------------------
__device__ __align__(128) u16 g_xo  [N_OBJ*FEAT];
__device__ __align__(128) u16 g_xp  [N_REL*FEAT];
__device__ __align__(128) u16 g_hob [N_OBJ*DIM];
__device__ __align__(128) u16 g_hpr [N_REL*DIM];
__device__ __align__(128) u16 g_pfh [N_REL*DIM];
__device__ __align__(128) u16 g_psh [N_REL*PS_P];
__device__ __align__(128) u16 g_ofh0[N_OBJ*DIM];
__device__ __align__(128) u16 g_ofh1[N_OBJ*DIM];
__device__ __align__(128) u16 g_oW1f[FEAT*DIM];
__device__ __align__(128) u16 g_oW2f[DIM*DIM];
__device__ __align__(128) u16 g_rW1f[FEAT*DIM];
__device__ __align__(128) u16 g_rW2f[DIM*DIM];
__device__ __align__(128) u16 g_Wcat01[DIM*2*DIM];
__device__ __align__(128) u16 g_Wcat23[DIM*2*DIM];
__device__ __align__(128) u16 g_WsoC[PS_P*2*SC_HALF];
__device__ __align__(128) u16 g_WpcP[DIM*PS_P];

// ---------------- helpers ------------------------------------------------------
__device__ __forceinline__ uint32_t smem_u32(const void* p) {
    uint32_t a;
    asm("{ .reg .u64 t; cvta.to.shared.u64 t, %1; cvt.u32.u64 %0, t; }" : "=r"(a) : "l"(p));
    return a;
}
__device__ __forceinline__ uint32_t pack_h2(float x, float y) {
    uint32_t d;
    asm("cvt.rn.f16x2.f32 %0, %1, %2;" : "=r"(d) : "f"(y), "f"(x));
    return d;
}
__device__ __forceinline__ void ldsm_x4(uint32_t* r, uint32_t addr) {
    asm volatile("ldmatrix.sync.aligned.m8n8.x4.shared.b16 {%0,%1,%2,%3}, [%4];"
                 : "=r"(r[0]), "=r"(r[1]), "=r"(r[2]), "=r"(r[3]) : "r"(addr));
}
__device__ __forceinline__ void ldsm_x4_t(uint32_t* r, uint32_t addr) {
    asm volatile("ldmatrix.sync.aligned.m8n8.x4.trans.shared.b16 {%0,%1,%2,%3}, [%4];"
                 : "=r"(r[0]), "=r"(r[1]), "=r"(r[2]), "=r"(r[3]) : "r"(addr));
}
__device__ __forceinline__ void mma16816(float* c, const uint32_t* a, uint32_t b0, uint32_t b1) {
    asm volatile("mma.sync.aligned.m16n8k16.row.col.f32.f16.f16.f32 "
                 "{%0,%1,%2,%3}, {%4,%5,%6,%7}, {%8,%9}, {%0,%1,%2,%3};"
                 : "+f"(c[0]), "+f"(c[1]), "+f"(c[2]), "+f"(c[3])
                 : "r"(a[0]), "r"(a[1]), "r"(a[2]), "r"(a[3]), "r"(b0), "r"(b1));
}
__device__ __forceinline__ void cp16(uint32_t dst, const void* src) {
    asm volatile("cp.async.cg.shared.global [%0], [%1], 16;" :: "r"(dst), "l"(src) : "memory");
}
#define CP_COMMIT() asm volatile("cp.async.commit_group;" ::: "memory")
#define CP_WAIT2()  asm volatile("cp.async.wait_group 2;" ::: "memory")

#define APITCH 80
#define BPITCH 272
#define ST_A   0
#define ST_B   10240
#define ST_SZ  18944
#define SMEM_GEMM (4*ST_SZ)

__device__ __forceinline__ void epi_quad(
    float* a, int r0, int r1, int c, int N, int doRelu,
    const float* bias, float* C, u16* Ch,
    float* saccB, int t0, int t1, int shalf, int side) {
    float b0 = bias[c], b1 = bias[c + 1];
    float v0 = a[0] + b0, v1 = a[1] + b1, v2 = a[2] + b0, v3 = a[3] + b1;
    if (doRelu) {
        v0 = fmaxf(v0, 0.0f); v1 = fmaxf(v1, 0.0f);
        v2 = fmaxf(v2, 0.0f); v3 = fmaxf(v3, 0.0f);
    }
    if (saccB) {
        const int col = c - side * shalf;
        atomicAdd(&saccB[(size_t)t0 * shalf + col],     v0);
        atomicAdd(&saccB[(size_t)t0 * shalf + col + 1], v1);
        atomicAdd(&saccB[(size_t)t1 * shalf + col],     v2);
        atomicAdd(&saccB[(size_t)t1 * shalf + col + 1], v3);
    } else {
        if (C) {
            *(float2*)(C + (size_t)r0 * N + c) = make_float2(v0, v1);
            *(float2*)(C + (size_t)r1 * N + c) = make_float2(v2, v3);
        }
        if (Ch) {
            *(uint32_t*)(Ch + (size_t)r0 * N + c) = pack_h2(v0, v1);
            *(uint32_t*)(Ch + (size_t)r1 * N + c) = pack_h2(v2, v3);
        }
    }
}

// ================== QUAD GEMM: CTA 128x128, 4 warps 64x64, K-tile 32, 4-stage ===
__global__ __launch_bounds__(128, 2)
void gemm_f16q(const u16* __restrict__ A, const u16* __restrict__ B,
               const float* __restrict__ bias, int M, int K, int N, int doRelu,
               float* __restrict__ C, u16* __restrict__ Ch,
               const int* __restrict__ rel, float* __restrict__ sacc, int shalf) {
    extern __shared__ __align__(128) char smem[];
    const uint32_t sb = smem_u32(smem);
    const int tid = threadIdx.x;
    const int lane = tid & 31;
    const int w = tid >> 5;
    const int warp_m = (w & 1) * 64;
    const int warp_n = (w >> 1) * 64;
    const int m0 = blockIdx.y * 128;
    const int n0 = blockIdx.x * 128;
    const int KT = K >> 5;

    float acc[32][4];
    #pragma unroll
    for (int i = 0; i < 32; i++)
        #pragma unroll
        for (int j = 0; j < 4; j++) acc[i][j] = 0.0f;

    auto issue = [&](int kt) {
        const uint32_t st = sb + (kt & 3) * ST_SZ;
        #pragma unroll
        for (int i = 0; i < 4; i++) {
            int idx = i * 128 + tid;
            int arow = idx >> 2, ac = idx & 3;
            size_t ga = (size_t)(m0 + arow) * K + kt * 32 + ac * 8;
            cp16(st + ST_A + (uint32_t)(arow * APITCH + ac * 16), A + ga);
        }
        #pragma unroll
        for (int i = 0; i < 4; i++) {
            int idx = i * 128 + tid;
            int brow = idx >> 4, bc = idx & 15;
            size_t gb = (size_t)(kt * 32 + brow) * N + n0 + bc * 8;
            cp16(st + ST_B + (uint32_t)(brow * BPITCH + bc * 16), B + gb);
        }
    };

    issue(0); CP_COMMIT();
    issue(1); CP_COMMIT();
    issue(2); CP_COMMIT();

    for (int kt = 0; kt < KT; kt++) {
        CP_WAIT2();
        __syncthreads();
        if (kt + 3 < KT) issue(kt + 3);
        CP_COMMIT();

        const uint32_t st = sb + (kt & 3) * ST_SZ;
        #pragma unroll
        for (int ks = 0; ks < 2; ks++) {
            uint32_t ah[4][4];
            const uint32_t a_off = (uint32_t)((warp_m + (lane & 15)) * APITCH
                                              + ks * 32 + (lane >> 4) * 16);
            #pragma unroll
            for (int mi = 0; mi < 4; mi++)
                ldsm_x4(ah[mi], st + ST_A + a_off + mi * 16 * APITCH);
            const uint32_t b_off = (uint32_t)((ks * 16 + (lane & 15)) * BPITCH
                                              + (warp_n + (lane >> 4) * 8) * 2);
            #pragma unroll
            for (int np = 0; np < 4; np++) {
                uint32_t bh[4];
                ldsm_x4_t(bh, st + ST_B + b_off + np * 32);
                #pragma unroll
                for (int mi = 0; mi < 4; mi++) {
                    #pragma unroll
                    for (int j = 0; j < 2; j++)
                        mma16816(acc[mi * 8 + np * 2 + j], ah[mi], bh[2*j], bh[2*j+1]);
                }
            }
        }
    }

    const int g = lane >> 2, tig = lane & 3;
    float* saccB = nullptr;
    int side = 0;
    if (sacc) { side = n0 / shalf; saccB = sacc + (size_t)side * N_OBJ * shalf; }
    #pragma unroll
    for (int mi = 0; mi < 4; mi++) {
        const int r0 = m0 + warp_m + mi * 16 + g;
        const int r1 = r0 + 8;
        int t0 = 0, t1 = 0;
        if (sacc) { t0 = rel[r0 * 2 + side]; t1 = rel[r1 * 2 + side]; }
        #pragma unroll
        for (int ni = 0; ni < 8; ni++) {
            const int c = n0 + warp_n + ni * 8 + tig * 2;
            epi_quad(acc[mi * 8 + ni], r0, r1, c, N, doRelu, bias, C, Ch,
                     saccB, t0, t1, shalf, side);
        }
    }
}

// ================== HALF-M GEMM: CTA 64x128, 4 warps 32x64, 4 CTA/SM ===========
#define HST_A 0
#define HST_B 5120
#define HST_SZ 13824

__global__ __launch_bounds__(128, 4)
void gemm_f16h(const u16* __restrict__ A, const u16* __restrict__ B,
               const float* __restrict__ bias, int M, int K, int N, int doRelu,
               float* __restrict__ C, u16* __restrict__ Ch) {
    extern __shared__ __align__(128) char smem[];
    const uint32_t sb = smem_u32(smem);
    const int tid = threadIdx.x;
    const int lane = tid & 31;
    const int w = tid >> 5;
    const int warp_m = (w & 1) * 32;
    const int warp_n = (w >> 1) * 64;
    const int m0 = blockIdx.y * 64;
    const int n0 = blockIdx.x * 128;
    const int KT = K >> 5;

    float acc[16][4];
    #pragma unroll
    for (int i = 0; i < 16; i++)
        #pragma unroll
        for (int j = 0; j < 4; j++) acc[i][j] = 0.0f;

    auto issue = [&](int kt) {
        const uint32_t st = sb + (kt & 3) * HST_SZ;
        #pragma unroll
        for (int i = 0; i < 2; i++) {
            int idx = i * 128 + tid;
            int arow = idx >> 2, ac = idx & 3;
            size_t ga = (size_t)(m0 + arow) * K + kt * 32 + ac * 8;
            cp16(st + HST_A + (uint32_t)(arow * APITCH + ac * 16), A + ga);
        }
        #pragma unroll
        for (int i = 0; i < 4; i++) {
            int idx = i * 128 + tid;
            int brow = idx >> 4, bc = idx & 15;
            size_t gb = (size_t)(kt * 32 + brow) * N + n0 + bc * 8;
            cp16(st + HST_B + (uint32_t)(brow * BPITCH + bc * 16), B + gb);
        }
    };

    issue(0); CP_COMMIT();
    issue(1); CP_COMMIT();
    issue(2); CP_COMMIT();

    for (int kt = 0; kt < KT; kt++) {
        CP_WAIT2();
        __syncthreads();
        if (kt + 3 < KT) issue(kt + 3);
        CP_COMMIT();

        const uint32_t st = sb + (kt & 3) * HST_SZ;
        #pragma unroll
        for (int ks = 0; ks < 2; ks++) {
            uint32_t ah[2][4];
            const uint32_t a_off = (uint32_t)((warp_m + (lane & 15)) * APITCH
                                              + ks * 32 + (lane >> 4) * 16);
            #pragma unroll
            for (int mi = 0; mi < 2; mi++)
                ldsm_x4(ah[mi], st + HST_A + a_off + mi * 16 * APITCH);
            const uint32_t b_off = (uint32_t)((ks * 16 + (lane & 15)) * BPITCH
                                              + (warp_n + (lane >> 4) * 8) * 2);
            #pragma unroll
            for (int np = 0; np < 4; np++) {
                uint32_t bh[4];
                ldsm_x4_t(bh, st + HST_B + b_off + np * 32);
                #pragma unroll
                for (int mi = 0; mi < 2; mi++) {
                    #pragma unroll
                    for (int j = 0; j < 2; j++)
                        mma16816(acc[mi * 8 + np * 2 + j], ah[mi], bh[2*j], bh[2*j+1]);
                }
            }
        }
    }

    const int g = lane >> 2, tig = lane & 3;
    #pragma unroll
    for (int mi = 0; mi < 2; mi++) {
        const int r0 = m0 + warp_m + mi * 16 + g;
        const int r1 = r0 + 8;
        #pragma unroll
        for (int ni = 0; ni < 8; ni++) {
            const int c = n0 + warp_n + ni * 8 + tig * 2;
            epi_quad(acc[mi * 8 + ni], r0, r1, c, N, doRelu, bias, C, Ch,
                     nullptr, 0, 0, 0, 0);
        }
    }
}

// ---------------- converters / packers ------------------------------------------
__global__ void conv_kernel(const float* __restrict__ x, u16* __restrict__ h, int n4) {
    int i = blockIdx.x * blockDim.x + threadIdx.x;
    if (i >= n4) return;
    float4 v = *(const float4*)(x + i * 4);
    uint2 o;
    o.x = pack_h2(v.x, v.y);
    o.y = pack_h2(v.z, v.w);
    *(uint2*)(h + i * 4) = o;
}
__global__ void packW_kernel(const float* __restrict__ W, u16* __restrict__ out, int base) {
    int i = blockIdx.x * blockDim.x + threadIdx.x;
    if (i >= DIM * DIM) return;
    int idx = i * 2;
    int k = idx >> 10, c = idx & 1023;
    int s = c >> 9, n = c & 511;
    const float* src = W + ((size_t)(base + s)) * DIM * DIM + (size_t)k * DIM + n;
    *(uint32_t*)(out + idx) = pack_h2(src[0], src[1]);
}
__global__ void packScore_kernel(const float* __restrict__ Wpc, const float* __restrict__ bpc,
                                 const float* __restrict__ Wso, const float* __restrict__ bso,
                                 const float* __restrict__ Wsr,
                                 u16* __restrict__ WpcP, float* __restrict__ bpcP,
                                 u16* __restrict__ WsoC, float* __restrict__ bsoC,
                                 float* __restrict__ WsrC) {
    int i = blockIdx.x * blockDim.x + threadIdx.x;
    if (i < DIM * PS_P) {
        int k = i >> 7, n = i & 127;
        float v = (n < NC_PRED) ? Wpc[k * NC_PRED + n] : 0.0f;
        __half h = __float2half(v);
        WpcP[i] = *(u16*)&h;
    }
    if (i < PS_P) bpcP[i] = (i < NC_PRED) ? bpc[i] : 0.0f;
    if (i < PS_P * 2 * SC_HALF) {
        int k = i >> 9, n = i & 511;
        int s = n >> 8, nn = n & 255;
        float v = (k < NC_PRED && nn < NC_OBJ) ? Wso[(size_t)s * NC_PRED * NC_OBJ + k * NC_OBJ + nn] : 0.0f;
        __half h = __float2half(v);
        WsoC[i] = *(u16*)&h;
    }
    if (i < 2 * SC_HALF) {
        int s = i >> 8, nn = i & 255;
        bsoC[i] = (nn < NC_OBJ) ? bso[s * NC_OBJ + nn] : 0.0f;
    }
    if (i < NC_OBJ * SR_N) {
        int k = i / SR_N, c = i - (i / SR_N) * SR_N;
        int s = (c >= NC_PRED) ? 1 : 0;
        int cc = c - s * NC_PRED;
        WsrC[i] = Wsr[(size_t)s * NC_OBJ * NC_PRED + k * NC_PRED + cc];
    }
}

// ---------------- tiled small GEMM (fp32, W in smem) ---------------------------
template<int NPAD, int RPT>
__global__ __launch_bounds__(256)
void wgemm_t(const float* __restrict__ A, const float* __restrict__ W,
             const float* __restrict__ bias, int K, int N, int KC, int doRelu,
             float* __restrict__ C,
             const int* __restrict__ rel, int sel, float* __restrict__ sacc) {
    extern __shared__ float sh[];
    float* Ws = sh;
    float* As = sh + (size_t)KC * N;
    const int tid = threadIdx.x;
    const int col = tid % NPAD;
    const int part = tid / NPAD;
    const int rbase = part * RPT;
    const int row0 = blockIdx.x * 32;
    const bool active = col < N;

    float acc[RPT];
    float b = active ? bias[col] : 0.0f;
    #pragma unroll
    for (int r = 0; r < RPT; r++) acc[r] = b;

    for (int k0 = 0; k0 < K; k0 += KC) {
        const int kc = (K - k0 < KC) ? (K - k0) : KC;
        for (int i = tid; i < kc * N; i += 256)
            Ws[i] = W[(size_t)k0 * N + i];
        for (int i = tid; i < 32 * kc; i += 256) {
            int rr = i / kc, kk = i - rr * kc;
            As[rr * KC + kk] = A[(size_t)(row0 + rr) * K + k0 + kk];
        }
        __syncthreads();
        if (active) {
            for (int k = 0; k < kc; k++) {
                float wv = Ws[k * N + col];
                #pragma unroll
                for (int r = 0; r < RPT; r++)
                    acc[r] = fmaf(As[(rbase + r) * KC + k], wv, acc[r]);
            }
        }
        __syncthreads();
    }

    if (active) {
        #pragma unroll
        for (int r = 0; r < RPT; r++) {
            int row = row0 + rbase + r;
            float v = acc[r];
            if (doRelu) v = fmaxf(v, 0.0f);
            if (sacc) {
                int t = rel[row * 2 + sel];
                atomicAdd(&sacc[(size_t)t * N + col], v);
            } else {
                C[(size_t)row * N + col] = v;
            }
        }
    }
}

// ---------------- small utility kernels --------------------------------------
__global__ void zero_kernel(float* p, int n) {
    int i = blockIdx.x * blockDim.x + threadIdx.x;
    if (i < n) p[i] = 0.0f;
}
__global__ void deg_kernel(const int* __restrict__ rel, float* __restrict__ deg) {
    int r = blockIdx.x * blockDim.x + threadIdx.x;
    if (r < N_REL) {
        atomicAdd(&deg[rel[2*r+0]], 1.0f);
        atomicAdd(&deg[N_OBJ + rel[2*r+1]], 1.0f);
    }
}
__global__ void rdeg_kernel(const float* __restrict__ deg, float* __restrict__ rdeg, int n) {
    int i = blockIdx.x * blockDim.x + threadIdx.x;
    if (i < n) rdeg[i] = 1.0f / (deg[i] + 1e-7f);
}
__global__ void update_o_kernel(const float* __restrict__ of, const float* __restrict__ a0,
                                const float* __restrict__ a1, const float* __restrict__ rdeg,
                                float* __restrict__ out, u16* __restrict__ oh,
                                int ncols, int apitch, int total) {
    int i = blockIdx.x * blockDim.x + threadIdx.x;
    if (i >= total) return;
    int r = i / ncols;
    int c = i - r * ncols;
    float v = of[i] + 0.5f * (a0[(size_t)r * apitch + c] * rdeg[r]
                            + a1[(size_t)r * apitch + c] * rdeg[N_OBJ + r]);
    out[i] = v;
    if (oh) {
        __half hv = __float2half(v);
        oh[i] = *(u16*)&hv;
    }
}
__global__ void update_p_kernel(const float* __restrict__ pf, const float* __restrict__ f0,
                                const float* __restrict__ f1, const int* __restrict__ rel,
                                float* __restrict__ out, u16* __restrict__ oh,
                                int ncols, int ppitch, int fpitch, int opitch, int hpitch,
                                int total) {
    int i = blockIdx.x * blockDim.x + threadIdx.x;
    if (i >= total) return;
    int r = i / ncols;
    int c = i - r * ncols;
    int s = rel[2*r+0];
    int o = rel[2*r+1];
    float v = pf[(size_t)r * ppitch + c]
            + 0.5f * (f0[(size_t)s * fpitch + c] + f1[(size_t)o * fpitch + c]) / (1.0f + 1e-7f);
    out[(size_t)r * opitch + c] = v;
    if (oh) {
        __half hv = __float2half(v);
        oh[(size_t)r * hpitch + c] = *(u16*)&hv;
    }
}

// ---------------- host launch helpers (stream-aware) ----------------------------
static inline void launch_zero(float* p, int n, cudaStream_t s) {
    zero_kernel<<<(n + 255) / 256, 256, 0, s>>>(p, n);
}
static inline void launch_conv(const float* x, u16* h, int n, cudaStream_t s) {
    conv_kernel<<<(n / 4 + 255) / 256, 256, 0, s>>>(x, h, n / 4);
}
static inline void launch_gemm_q(const u16* A, const u16* B, const float* b,
                                 int M, int K, int N, int relu,
                                 float* C, u16* Ch, const int* rel, float* sacc, int shalf,
                                 cudaStream_t s) {
    dim3 grid(N / 128, M / 128);
    gemm_f16q<<<grid, 128, SMEM_GEMM, s>>>(A, B, b, M, K, N, relu, C, Ch, rel, sacc, shalf);
}
static inline void launch_gemm_h(const u16* A, const u16* B, const float* b,
                                 int M, int K, int N, int relu, float* C, u16* Ch,
                                 cudaStream_t s) {
    dim3 grid(N / 128, M / 64);
    gemm_f16h<<<grid, 128, 4 * HST_SZ, s>>>(A, B, b, M, K, N, relu, C, Ch);
}
template<int NPAD, int RPT>
static inline void launch_wgemm_t(const float* A, const float* W, const float* b,
                                  int M, int K, int N, int relu,
                                  float* C, const int* rel, int sel, float* sacc,
                                  cudaStream_t s) {
    int KC = K;
    size_t bytes = ((size_t)KC * N + 32 * KC) * 4;
    if (bytes > 190 * 1024) {
        KC = 256;
        bytes = ((size_t)KC * N + 32 * KC) * 4;
    }
    wgemm_t<NPAD, RPT><<<M / 32, 256, bytes, s>>>(A, W, b, K, N, KC, relu, C, rel, sel, sacc);
}
template <typename T>
static inline T* sym(const void* s) {
    void* p = nullptr;
    cudaGetSymbolAddress(&p, s);
    return (T*)p;
}

extern "C" void kernel_launch(void* const* d_in, const int* in_sizes, int n_in,
                              void* d_out, int out_size) {
    const float* x_obj_raw  = (const float*)d_in[0];
    const float* x_pred_raw = (const float*)d_in[1];
    const int*   rel        = (const int*)  d_in[2];
    const float* oW1 = (const float*)d_in[3],  *ob1 = (const float*)d_in[4];
    const float* oW2 = (const float*)d_in[5],  *ob2 = (const float*)d_in[6];
    const float* rW1 = (const float*)d_in[7],  *rb1 = (const float*)d_in[8];
    const float* rW2 = (const float*)d_in[9],  *rb2 = (const float*)d_in[10];
    const float* Wcf = (const float*)d_in[11], *bcf = (const float*)d_in[12];
    const float* Wso = (const float*)d_in[13], *bso = (const float*)d_in[14];
    const float* Wsr = (const float*)d_in[15], *bsr = (const float*)d_in[16];
    const float* Woc = (const float*)d_in[17], *boc = (const float*)d_in[18];
    const float* Wpc = (const float*)d_in[19], *bpc = (const float*)d_in[20];
    float* out = (float*)d_out;

    cudaFuncSetAttribute(gemm_f16q, cudaFuncAttributeMaxDynamicSharedMemorySize, SMEM_GEMM);
    cudaFuncSetAttribute(gemm_f16h, cudaFuncAttributeMaxDynamicSharedMemorySize, 4 * HST_SZ);
    cudaFuncSetAttribute(wgemm_t<256, 32>, cudaFuncAttributeMaxDynamicSharedMemorySize, 195 * 1024);
    cudaFuncSetAttribute(wgemm_t<128, 16>, cudaFuncAttributeMaxDynamicSharedMemorySize, 195 * 1024);

    static cudaStream_t s1 = nullptr;
    static cudaEvent_t ev[10];
    static bool init_ok = false;
    if (!init_ok) {
        bool ok = (cudaStreamCreateWithFlags(&s1, cudaStreamNonBlocking) == cudaSuccess);
        for (int i = 0; i < 10 && ok; i++)
            ok = (cudaEventCreateWithFlags(&ev[i], cudaEventDisableTiming) == cudaSuccess);
        if (!ok) s1 = nullptr;
        init_ok = true;
    }
    const cudaStream_t s0 = 0;
    const cudaStream_t sx = s1 ? s1 : s0;
    const bool dual = (s1 != nullptr);
    auto fork = [&](int i) { if (dual) { cudaEventRecord(ev[i], s0); cudaStreamWaitEvent(sx, ev[i], 0); } };
    auto join = [&](int i) { if (dual) { cudaEventRecord(ev[i], sx); cudaStreamWaitEvent(s0, ev[i], 0); } };

    float* pfA     = sym<float>(g_pfeatA);
    float* pfB     = sym<float>(g_pfeatB);
    float* ofA     = sym<float>(g_ofeatA);
    float* ofB     = sym<float>(g_ofeatB);
    float* fcoCat  = sym<float>(g_fcoCat);
    float* fcoCat2 = sym<float>(g_fcoCat2);
    float* accCat  = sym<float>(g_accCat);
    float* osA     = sym<float>(g_osA);
    float* osB     = sym<float>(g_osB);
    float* psA     = sym<float>(g_psA);
    float* psB     = sym<float>(g_psB);
    float* fcsC    = sym<float>(g_fcsC);
    float* fcsC2   = sym<float>(g_fcsC2);
    float* rdeg    = sym<float>(g_rdeg);
    float* deg     = sym<float>(g_deg);
    float* bsoC    = sym<float>(g_bsoC);
    float* bpcP    = sym<float>(g_bpcP);
    float* WsrC    = sym<float>(g_WsrC);

    u16* xo  = sym<u16>(g_xo);
    u16* xp  = sym<u16>(g_xp);
    u16* hob = sym<u16>(g_hob);
    u16* hpr = sym<u16>(g_hpr);
    u16* pfh = sym<u16>(g_pfh);
    u16* psh = sym<u16>(g_psh);
    u16* ofh[2] = { sym<u16>(g_ofh0), sym<u16>(g_ofh1) };
    u16* oW1f = sym<u16>(g_oW1f);
    u16* oW2f = sym<u16>(g_oW2f);
    u16* rW1f = sym<u16>(g_rW1f);
    u16* rW2f = sym<u16>(g_rW2f);
    u16* Wcat01 = sym<u16>(g_Wcat01);
    u16* Wcat23 = sym<u16>(g_Wcat23);
    u16* WsoC = sym<u16>(g_WsoC);
    u16* WpcP = sym<u16>(g_WpcP);

    // ---- degrees + operand conversion / weight packing (s0) ----
    launch_zero(deg, 2 * N_OBJ, s0);
    deg_kernel<<<(N_REL + 255) / 256, 256, 0, s0>>>(rel, deg);
    rdeg_kernel<<<(2 * N_OBJ + 255) / 256, 256, 0, s0>>>(deg, rdeg, 2 * N_OBJ);
    launch_conv(x_obj_raw,  xo, N_OBJ * FEAT, s0);
    launch_conv(x_pred_raw, xp, N_REL * FEAT, s0);
    launch_conv(oW1, oW1f, FEAT * DIM, s0);
    launch_conv(oW2, oW2f, DIM * DIM, s0);
    launch_conv(rW1, rW1f, FEAT * DIM, s0);
    launch_conv(rW2, rW2f, DIM * DIM, s0);
    packW_kernel<<<(DIM * DIM + 255) / 256, 256, 0, s0>>>(Wcf, Wcat01, 0);
    packW_kernel<<<(DIM * DIM + 255) / 256, 256, 0, s0>>>(Wcf, Wcat23, 2);
    packScore_kernel<<<(PS_P * 2 * SC_HALF + 255) / 256, 256, 0, s0>>>(
        Wpc, bpc, Wso, bso, Wsr, WpcP, bpcP, WsoC, bsoC, WsrC);

    fork(0);   // sx waits for convs/packs

    // ---- embedding MLPs: obj chain + gather-st0 on sx; pred chain on s0 ----
    launch_gemm_h(xo,  oW1f, ob1, N_OBJ, FEAT, DIM, 1, nullptr, hob, sx);
    launch_gemm_h(hob, oW2f, ob2, N_OBJ, DIM,  DIM, 0, ofA,     ofh[0], sx);
    launch_gemm_h(ofh[0], Wcat23, bcf + 2 * DIM, N_OBJ, DIM, 2 * DIM, 1,
                  fcoCat, nullptr, sx);

    launch_gemm_q(xp,  rW1f, rb1, N_REL, FEAT, DIM, 1, nullptr, hpr, nullptr, nullptr, 512, s0);
    launch_gemm_q(hpr, rW2f, rb2, N_REL, DIM,  DIM, 0, out,     pfh, nullptr, nullptr, 512, s0);

    // ---- feature-level aGCN step 0 ----
    launch_zero(accCat, 2 * N_OBJ * DIM, s0);
    launch_gemm_q(pfh, Wcat01, bcf, N_REL, DIM, 2 * DIM, 1,
                  nullptr, nullptr, rel, accCat, DIM, s0);
    join(1);   // s0 <- sx: ofA/ofh0/fcoCat ready
    update_o_kernel<<<(N_OBJ * DIM + 255) / 256, 256, 0, s0>>>(
        ofA, accCat, accCat + N_OBJ * DIM, rdeg, ofB, ofh[1], DIM, DIM, N_OBJ * DIM);
    fork(2);   // sx <- s0: ofh[1] ready
    // gather st1 writes its OWN buffer fcoCat2 (fixes R16 race vs update_p st0's
    // concurrent read of fcoCat)
    launch_gemm_h(ofh[1], Wcat23, bcf + 2 * DIM, N_OBJ, DIM, 2 * DIM, 1,
                  fcoCat2, nullptr, sx);
    update_p_kernel<<<(N_REL * DIM + 255) / 256, 256, 0, s0>>>(
        out, fcoCat, fcoCat + DIM, rel, pfB, pfh, DIM, DIM, 2 * DIM, DIM, DIM, N_REL * DIM);

    // ---- feature-level aGCN step 1 ----
    launch_zero(accCat, 2 * N_OBJ * DIM, s0);
    launch_gemm_q(pfh, Wcat01, bcf, N_REL, DIM, 2 * DIM, 1,
                  nullptr, nullptr, rel, accCat, DIM, s0);
    update_o_kernel<<<(N_OBJ * DIM + 255) / 256, 256, 0, s0>>>(
        ofB, accCat, accCat + N_OBJ * DIM, rdeg, ofA, ofh[0], DIM, DIM, N_OBJ * DIM);
    join(3);   // s0 <- sx: fcoCat2 ready
    update_p_kernel<<<(N_REL * DIM + 255) / 256, 256, 0, s0>>>(
        pfB, fcoCat2, fcoCat2 + DIM, rel, pfA, pfh, DIM, DIM, 2 * DIM, DIM, DIM, N_REL * DIM);

    // ---- classifiers: obj on sx, pred on s0 ----
    fork(4);   // sx <- s0: ofA (final of) ready
    launch_wgemm_t<256, 32>(ofA, Woc, boc, N_OBJ, DIM, NC_OBJ, 0, osA,
                            nullptr, 0, nullptr, sx);
    launch_wgemm_t<128, 16>(osA, WsrC, bsr, N_OBJ, NC_OBJ, SR_N, 1,
                            fcsC, nullptr, 0, nullptr, sx);
    launch_gemm_q(pfh, WpcP, bpcP, N_REL, DIM, PS_P, 0, psA, psh,
                  nullptr, nullptr, 512, s0);

    // ---- score-level aGCN ----
    float* outO = out + (size_t)N_REL * DIM;
    float* outP = out + (size_t)N_REL * DIM + N_OBJ * NC_OBJ;

    // step 0
    launch_zero(accCat, 2 * N_OBJ * SC_HALF, s0);
    launch_gemm_q(psh, WsoC, bsoC, N_REL, PS_P, 2 * SC_HALF, 1,
                  nullptr, nullptr, rel, accCat, SC_HALF, s0);
    join(5);   // s0 <- sx: osA + fcsC ready
    update_o_kernel<<<(N_OBJ * NC_OBJ + 255) / 256, 256, 0, s0>>>(
        osA, accCat, accCat + N_OBJ * SC_HALF, rdeg, osB, nullptr,
        NC_OBJ, SC_HALF, N_OBJ * NC_OBJ);
    update_p_kernel<<<(N_REL * NC_PRED + 255) / 256, 256, 0, s0>>>(
        psA, fcsC, fcsC + NC_PRED, rel, psB, psh,
        NC_PRED, PS_P, SR_N, PS_P, PS_P, N_REL * NC_PRED);
    fork(6);   // sx <- s0: osB ready
    // step-1 gather writes its own buffer fcsC2 (belt & braces vs fcsC reuse)
    launch_wgemm_t<128, 16>(osB, WsrC, bsr, N_OBJ, NC_OBJ, SR_N, 1,
                            fcsC2, nullptr, 0, nullptr, sx);

    // step 1
    launch_zero(accCat, 2 * N_OBJ * SC_HALF, s0);
    launch_gemm_q(psh, WsoC, bsoC, N_REL, PS_P, 2 * SC_HALF, 1,
                  nullptr, nullptr, rel, accCat, SC_HALF, s0);
    update_o_kernel<<<(N_OBJ * NC_OBJ + 255) / 256, 256, 0, s0>>>(
        osB, accCat, accCat + N_OBJ * SC_HALF, rdeg, outO, nullptr,
        NC_OBJ, SC_HALF, N_OBJ * NC_OBJ);
    join(7);   // s0 <- sx: fcsC2 ready
    update_p_kernel<<<(N_REL * NC_PRED + 255) / 256, 256, 0, s0>>>(
        psB, fcsC2, fcsC2 + NC_PRED, rel, outP, nullptr,
        NC_PRED, PS_P, SR_N, NC_PRED, PS_P, N_REL * NC_PRED);
}